// round 11
// baseline (speedup 1.0000x reference)
#include <cuda_runtime.h>
#include <cuda_bf16.h>

// RWKV single-token inference, fp32 — persistent kernel (148x256).
// R11: 6-slot-per-warp cp.async pipeline, cross-phase issue schedule,
// dummy-commit count normalization. D=1024, H=4096, L=24, V=50277.

#define D    1024
#define HD   4096
#define NL   24
#define NV   50277
#define GRID 148
#define NTH  256
#define NWARP 8
#define TOTW (GRID * NWARP)   // 1184 warps

#define SBUF_F   4096                  // 16KB shared vector region (floats)
#define WSLOT_F  1024                  // 4KB per slot (floats)
#define NSLOT    6
#define SMEM_DYN ((SBUF_F + NWARP * NSLOT * WSLOT_F) * 4)   // 208KB

__device__ __align__(16) float g_x[D];
__device__ __align__(16) float g_rwkv[D];
__device__ __align__(16) float g_kk[HD];
__device__ __align__(16) float g_r2[D];
__device__ __align__(16) float g_state_scratch[NL * 5 * D];
__device__ unsigned g_count;
__device__ unsigned g_gen;

__device__ __forceinline__ float warp_sum(float s) {
#pragma unroll
    for (int o = 16; o > 0; o >>= 1) s += __shfl_xor_sync(0xffffffffu, s, o);
    return s;
}

__device__ __forceinline__ float block_sum256(float v, float* sred) {
    __syncthreads();
    v = warp_sum(v);
    int warp = threadIdx.x >> 5, lane = threadIdx.x & 31;
    if (lane == 0) sred[warp] = v;
    __syncthreads();
    float t = 0.f;
#pragma unroll
    for (int w = 0; w < NWARP; w++) t += sred[w];
    return t;
}

// Grid barrier, acq/rel atomics (148 blocks co-resident, 1 CTA/SM).
__device__ __forceinline__ void grid_barrier() {
    __syncthreads();
    if (threadIdx.x == 0) {
        unsigned gen;
        asm volatile("ld.global.relaxed.gpu.u32 %0, [%1];" : "=r"(gen) : "l"(&g_gen));
        unsigned old;
        asm volatile("atom.global.add.acq_rel.gpu.u32 %0, [%1], 1;"
                     : "=r"(old) : "l"(&g_count) : "memory");
        if (old == GRID - 1) {
            asm volatile("st.global.relaxed.gpu.u32 [%0], %1;" :: "l"(&g_count), "r"(0u) : "memory");
            asm volatile("st.global.release.gpu.u32 [%0], %1;" :: "l"(&g_gen), "r"(gen + 1u) : "memory");
        } else {
            unsigned cur;
            do {
                __nanosleep(20);
                asm volatile("ld.global.acquire.gpu.u32 %0, [%1];" : "=r"(cur) : "l"(&g_gen) : "memory");
            } while (cur == gen);
        }
    }
    __syncthreads();
}

// Issue one 4KB row (1024 floats) into shared via cp.async (8x16B per lane).
__device__ __forceinline__ void cpa_row(unsigned dst, const float* __restrict__ src, int lane) {
    unsigned d = dst + (unsigned)lane * 16u;
    const char* s = (const char*)src + lane * 16;
#pragma unroll
    for (int j = 0; j < 8; j++)
        asm volatile("cp.async.cg.shared.global [%0], [%1], 16;"
                     :: "r"(d + 512u * j), "l"(s + 512 * j) : "memory");
}
#define CPA_COMMIT() asm volatile("cp.async.commit_group;" ::: "memory")
#define CPA_WAIT(n)  asm volatile("cp.async.wait_group %0;" :: "n"(n) : "memory")

__device__ __forceinline__ float dot_ss(const float4* __restrict__ w4,
                                        const float4* __restrict__ v4, int lane) {
    float s = 0.f;
#pragma unroll
    for (int j = 0; j < 8; j++) {
        float4 a = w4[lane + 32 * j];
        float4 b = v4[lane + 32 * j];
        s = fmaf(a.x, b.x, s); s = fmaf(a.y, b.y, s);
        s = fmaf(a.z, b.z, s); s = fmaf(a.w, b.w, s);
    }
    return s;
}

__device__ __forceinline__ void ln_block(const float* __restrict__ w,
                                         const float* __restrict__ b,
                                         float* sred, float out[4]) {
    int t = threadIdx.x;
    float4 xv = __ldcg((const float4*)g_x + t);
    float mu = block_sum256(xv.x + xv.y + xv.z + xv.w, sred) * (1.f / D);
    float xa[4]; *(float4*)xa = xv;
    float da[4], vs = 0.f;
#pragma unroll
    for (int c = 0; c < 4; c++) { da[c] = xa[c] - mu; vs += da[c] * da[c]; }
    float var = block_sum256(vs, sred) * (1.f / D);
    float rstd = rsqrtf(var + 1e-5f);
    float wa[4], ba[4];
    *(float4*)wa = ((const float4*)w)[t];
    *(float4*)ba = ((const float4*)b)[t];
#pragma unroll
    for (int c = 0; c < 4; c++) out[c] = da[c] * rstd * wa[c] + ba[c];
}

__global__ __launch_bounds__(NTH, 1) void rwkv_fused(
    const int* __restrict__ token, const float* __restrict__ state,
    const float* __restrict__ emb,
    const float* __restrict__ ln0_w, const float* __restrict__ ln0_b,
    const float* __restrict__ ln1_w, const float* __restrict__ ln1_b,
    const float* __restrict__ ln2_w, const float* __restrict__ ln2_b,
    const float* __restrict__ kw, const float* __restrict__ vw,
    const float* __restrict__ rw, const float* __restrict__ ow,
    const float* __restrict__ mk, const float* __restrict__ mv,
    const float* __restrict__ mr,
    const float* __restrict__ tf, const float* __restrict__ td,
    const float* __restrict__ fkw, const float* __restrict__ fvw,
    const float* __restrict__ frw,
    const float* __restrict__ fmk, const float* __restrict__ fmr,
    const float* __restrict__ lnw, const float* __restrict__ lnb,
    const float* __restrict__ head,
    float* __restrict__ logits, float* __restrict__ state_out) {
    __shared__ float sred[NWARP];
    extern __shared__ __align__(16) float dsm[];
    float* s_buf = dsm;                                             // 16KB
    float* wbuf  = dsm + SBUF_F + (threadIdx.x >> 5) * (NSLOT * WSLOT_F);
    const unsigned wb_u32 = (unsigned)__cvta_generic_to_shared(wbuf);

    const int t = threadIdx.x, warp = t >> 5, lane = t & 31, bid = blockIdx.x;
    const int wg = bid * NWARP + warp;          // 0..1183
    const bool act128 = (bid < 128);
    const int row = wg;

#define SLOT_PTR(i) ((const float4*)(wbuf + (i) * WSLOT_F))
#define SLOT_U32(i) (wb_u32 + (unsigned)(i) * 4096u)

    // ---- embed: block 0 computes g_x = LN0(emb[token]) ----
    if (bid == 0) {
        float4 xv = ((const float4*)(emb + (size_t)token[0] * D))[t];
        float mu = block_sum256(xv.x + xv.y + xv.z + xv.w, sred) * (1.f / D);
        float dx = xv.x - mu, dy = xv.y - mu, dz = xv.z - mu, dw = xv.w - mu;
        float var = block_sum256(dx * dx + dy * dy + dz * dz + dw * dw, sred) * (1.f / D);
        float rstd = rsqrtf(var + 1e-5f);
        float4 wv = ((const float4*)ln0_w)[t];
        float4 bv = ((const float4*)ln0_b)[t];
        float4 o;
        o.x = dx * rstd * wv.x + bv.x;
        o.y = dy * rstd * wv.y + bv.y;
        o.z = dz * rstd * wv.z + bv.z;
        o.w = dw * rstd * wv.w + bv.w;
        ((float4*)g_x)[t] = o;
    }

    for (int l = 0; l < NL; l++) {
        const size_t lo = (size_t)l * D;
        const size_t sb = (size_t)l * 5 * D;
        const float* fk_base = fkw + (size_t)l * HD * D;
        const int u1 = wg + TOTW, u2 = wg + 2 * TOTW, u3 = wg + 3 * TOTW, u4 = wg + 4 * TOTW;
        const bool has5 = (u4 < HD + D);   // wg < 384
        const float* fv_row = fvw + (size_t)l * D * HD + (size_t)row * HD;

        // ---- layer-top issues ----
        if (act128) {
            // groups: 1=k 2=v 3=r 4=ow 5=u0 6=u1            pending 6
            cpa_row(SLOT_U32(0), kw + lo * D + (size_t)row * D, lane); CPA_COMMIT();
            cpa_row(SLOT_U32(1), vw + lo * D + (size_t)row * D, lane); CPA_COMMIT();
            cpa_row(SLOT_U32(2), rw + lo * D + (size_t)row * D, lane); CPA_COMMIT();
            cpa_row(SLOT_U32(3), ow + lo * D + (size_t)row * D, lane); CPA_COMMIT();
            cpa_row(SLOT_U32(4), fk_base + (size_t)wg * D, lane);      CPA_COMMIT();
            cpa_row(SLOT_U32(5), fk_base + (size_t)u1 * D, lane);      CPA_COMMIT();
        } else {
            // groups: 1=u0 2=u1                              pending 2
            cpa_row(SLOT_U32(4), fk_base + (size_t)wg * D, lane); CPA_COMMIT();
            cpa_row(SLOT_U32(5), fk_base + (size_t)u1 * D, lane); CPA_COMMIT();
        }

        // ================= Phase A: time mixing =================
        grid_barrier();   // g_x final
        if (act128) {
            float xn4[4];
            ln_block(ln1_w + lo, ln1_b + lo, sred, xn4);
            float mka[4], mva[4], mra[4], sxa[4];
            *(float4*)mka = ((const float4*)(mk + lo))[t];
            *(float4*)mva = ((const float4*)(mv + lo))[t];
            *(float4*)mra = ((const float4*)(mr + lo))[t];
            *(float4*)sxa = ((const float4*)(state + sb + D))[t];  // sx_att
            int base = 4 * t;
#pragma unroll
            for (int c = 0; c < 4; c++) {
                float xn = xn4[c];
                s_buf[base + c]         = xn * mka[c] + sxa[c] * (1.f - mka[c]);
                s_buf[D + base + c]     = xn * mva[c] + sxa[c] * (1.f - mva[c]);
                s_buf[2 * D + base + c] = xn * mra[c] + sxa[c] * (1.f - mra[c]);
                if (bid == 0) state_out[sb + D + base + c] = xn;   // state row 1
            }
            __syncthreads();

            CPA_WAIT(3);   // k,v,r landed; pending: ow,u0,u1
            float sk = warp_sum(dot_ss(SLOT_PTR(0), (const float4*)s_buf, lane));
            float sv = warp_sum(dot_ss(SLOT_PTR(1), (const float4*)(s_buf + D), lane));
            float sr = warp_sum(dot_ss(SLOT_PTR(2), (const float4*)(s_buf + 2 * D), lane));

            if (lane == 0) {
                float aa = state[sb + 2 * D + row];
                float bb = state[sb + 3 * D + row];
                float pp = state[sb + 4 * D + row];
                float tfv = tf[lo + row];
                float tdv = td[lo + row];
                float k = sk, v = sv;
                float rs = 1.f / (1.f + expf(-sr));

                float ww = tfv + k;
                float qq = fmaxf(pp, ww);
                float e1 = expf(pp - qq);
                float e2 = expf(ww - qq);
                g_rwkv[row] = rs * (e1 * aa + e2 * v) / (e1 * bb + e2);

                float ww2 = pp + tdv;
                float qq2 = fmaxf(ww2, k);
                float e1b = expf(ww2 - qq2);
                float e2b = expf(k - qq2);
                state_out[sb + 2 * D + row] = e1b * aa + e2b * v;
                state_out[sb + 3 * D + row] = e1b * bb + e2b;
                state_out[sb + 4 * D + row] = qq2;
            }
        }

        // ================= Phase B: x += ow @ rwkv =================
        grid_barrier();   // g_rwkv complete
        if (act128) {
            ((float4*)s_buf)[t] = __ldcg((const float4*)g_rwkv + t);
            __syncthreads();
            CPA_WAIT(2);   // ow landed; pending: u0,u1
            float s = warp_sum(dot_ss(SLOT_PTR(3), (const float4*)s_buf, lane));
            if (lane == 0) g_x[row] = __ldcg(g_x + row) + s;
            // issue u2,u3,u4|dummy -> pending 5
            cpa_row(SLOT_U32(0), fk_base + (size_t)u2 * D, lane); CPA_COMMIT();
            {
                const float* r3 = (u3 < HD) ? fk_base + (size_t)u3 * D
                                            : frw + lo * D + (size_t)(u3 - HD) * D;
                cpa_row(SLOT_U32(1), r3, lane); CPA_COMMIT();
            }
            if (has5) { cpa_row(SLOT_U32(2), frw + lo * D + (size_t)(u4 - HD) * D, lane); }
            CPA_COMMIT();  // real or dummy -> pending 5 either way
        } else {
            // issue u2,u3 -> pending 4
            cpa_row(SLOT_U32(0), fk_base + (size_t)u2 * D, lane); CPA_COMMIT();
            cpa_row(SLOT_U32(1), frw + lo * D + (size_t)(u3 - HD) * D, lane); CPA_COMMIT();
        }

        // ================= Phase C: channel mix 1 =================
        grid_barrier();   // g_x updated by phase B
        {
            float xn4[4];
            ln_block(ln2_w + lo, ln2_b + lo, sred, xn4);
            float mka[4], mra[4], sxa[4];
            *(float4*)mka = ((const float4*)(fmk + lo))[t];
            *(float4*)mra = ((const float4*)(fmr + lo))[t];
            *(float4*)sxa = ((const float4*)(state + sb))[t];      // sx_ffn
            int base = 4 * t;
#pragma unroll
            for (int c = 0; c < 4; c++) {
                float xn = xn4[c];
                s_buf[base + c]     = xn * mka[c] + sxa[c] * (1.f - mka[c]);
                s_buf[D + base + c] = xn * mra[c] + sxa[c] * (1.f - mra[c]);
                if (bid == 0) state_out[sb + base + c] = xn;       // state row 0
            }
            __syncthreads();

            const float4* xk4 = (const float4*)s_buf;
            const float4* xr4 = (const float4*)(s_buf + D);
            if (act128) {
                // pending 5: u0,u1,u2,u3,u4|dummy
                CPA_WAIT(4);                                   // u0 done
                float s0 = warp_sum(dot_ss(SLOT_PTR(4), xk4, lane));
                cpa_row(SLOT_U32(4), fv_row, lane); CPA_COMMIT();          // D0
                if (lane == 0) { float rl = fmaxf(s0, 0.f); g_kk[wg] = rl * rl; }

                CPA_WAIT(4);                                   // u1 done
                float s1 = warp_sum(dot_ss(SLOT_PTR(5), xk4, lane));
                cpa_row(SLOT_U32(5), fv_row + 1024, lane); CPA_COMMIT();   // D1
                if (lane == 0) { float rl = fmaxf(s1, 0.f); g_kk[u1] = rl * rl; }

                CPA_WAIT(4);                                   // u2 done
                float s2 = warp_sum(dot_ss(SLOT_PTR(0), xk4, lane));
                cpa_row(SLOT_U32(0), fv_row + 2048, lane); CPA_COMMIT();   // D2
                if (lane == 0) { float rl = fmaxf(s2, 0.f); g_kk[u2] = rl * rl; }

                CPA_WAIT(4);                                   // u3 done
                float s3 = warp_sum(dot_ss(SLOT_PTR(1), (u3 < HD) ? xk4 : xr4, lane));
                cpa_row(SLOT_U32(1), fv_row + 3072, lane); CPA_COMMIT();   // D3
                if (lane == 0) {
                    if (u3 < HD) { float rl = fmaxf(s3, 0.f); g_kk[u3] = rl * rl; }
                    else g_r2[u3 - HD] = 1.f / (1.f + expf(-s3));
                }

                CPA_WAIT(4);                                   // u4|dummy done
                if (has5) {
                    float s4 = warp_sum(dot_ss(SLOT_PTR(2), xr4, lane));
                    if (lane == 0) g_r2[u4 - HD] = 1.f / (1.f + expf(-s4));
                }
                // pending 4: D0..D3 — land during barrier D + kk copy
            } else {
                // pending 4: u0,u1,u2,u3
                CPA_WAIT(3);
                float s0 = warp_sum(dot_ss(SLOT_PTR(4), xk4, lane));
                if (lane == 0) { float rl = fmaxf(s0, 0.f); g_kk[wg] = rl * rl; }
                CPA_WAIT(2);
                float s1 = warp_sum(dot_ss(SLOT_PTR(5), xk4, lane));
                if (lane == 0) { float rl = fmaxf(s1, 0.f); g_kk[u1] = rl * rl; }
                CPA_WAIT(1);
                float s2 = warp_sum(dot_ss(SLOT_PTR(0), xk4, lane));
                if (lane == 0) { float rl = fmaxf(s2, 0.f); g_kk[u2] = rl * rl; }
                CPA_WAIT(0);
                float s3 = warp_sum(dot_ss(SLOT_PTR(1), xr4, lane));   // u3 >= HD here
                if (lane == 0) g_r2[u3 - HD] = 1.f / (1.f + expf(-s3));
            }
        }

        // ================= Phase D: x += r2 * (fvw @ kk) =================
        grid_barrier();   // g_kk, g_r2 complete
        {
            if (act128) {
#pragma unroll
                for (int j = 0; j < 4; j++)
                    ((float4*)s_buf)[t + NTH * j] = __ldcg((const float4*)g_kk + t + NTH * j);
            }
            __syncthreads();
            if (act128) {
                const float4* k4 = (const float4*)s_buf;
                CPA_WAIT(3);
                float s = dot_ss(SLOT_PTR(4), k4, lane);
                CPA_WAIT(2);
                s += dot_ss(SLOT_PTR(5), k4 + 256, lane);
                CPA_WAIT(1);
                s += dot_ss(SLOT_PTR(0), k4 + 512, lane);
                CPA_WAIT(0);
                s += dot_ss(SLOT_PTR(1), k4 + 768, lane);
                s = warp_sum(s);
                if (lane == 0) g_x[row] = __ldcg(g_x + row) + __ldcg(g_r2 + row) * s;
            }
        }
    }

    // ================= Head: logits = head @ LN(x) =================
    // depth-6 rolling pipeline; dummy commits in the tail keep counts uniform.
#pragma unroll
    for (int i = 0; i < NSLOT; i++) {
        cpa_row(SLOT_U32(i), head + (size_t)(wg + i * TOTW) * D, lane);
        CPA_COMMIT();
    }   // pending 6 (wg+5*TOTW = 7103 < NV, always valid)
    grid_barrier();   // g_x final
    {
        float xn4[4];
        ln_block(lnw, lnb, sred, xn4);
        int base = 4 * t;
#pragma unroll
        for (int c = 0; c < 4; c++) s_buf[base + c] = xn4[c];
        __syncthreads();

        const float4* x4 = (const float4*)s_buf;
        int i = 0;
        for (int v = wg; v < NV; v += TOTW, i++) {
            CPA_WAIT(5);   // oldest of 6 done
            int slot = i % NSLOT;
            float s = warp_sum(dot_ss(SLOT_PTR(slot), x4, lane));
            int vn = v + NSLOT * TOTW;
            if (vn < NV) cpa_row(SLOT_U32(slot), head + (size_t)vn * D, lane);
            CPA_COMMIT();  // real or dummy -> pending back to 6
            if (lane == 0) logits[v] = s;
        }
    }
}

// ---------------------------------------------------------------------------
extern "C" void kernel_launch(void* const* d_in, const int* in_sizes, int n_in,
                              void* d_out, int out_size) {
    const int*   token     = (const int*)d_in[0];
    const float* state     = (const float*)d_in[1];
    const float* emb       = (const float*)d_in[2];
    const float* ln0_w     = (const float*)d_in[3];
    const float* ln0_b     = (const float*)d_in[4];
    const float* ln1_w     = (const float*)d_in[5];
    const float* ln1_b     = (const float*)d_in[6];
    const float* ln2_w     = (const float*)d_in[7];
    const float* ln2_b     = (const float*)d_in[8];
    const float* att_key   = (const float*)d_in[9];
    const float* att_value = (const float*)d_in[10];
    const float* att_recep = (const float*)d_in[11];
    const float* att_out   = (const float*)d_in[12];
    const float* tm_k      = (const float*)d_in[13];
    const float* tm_v      = (const float*)d_in[14];
    const float* tm_r      = (const float*)d_in[15];
    const float* t_first   = (const float*)d_in[16];
    const float* t_decay   = (const float*)d_in[17];
    const float* ffn_key   = (const float*)d_in[18];
    const float* ffn_value = (const float*)d_in[19];
    const float* ffn_recep = (const float*)d_in[20];
    const float* ffn_tm_k  = (const float*)d_in[21];
    const float* ffn_tm_r  = (const float*)d_in[22];
    const float* lnout_w   = (const float*)d_in[23];
    const float* lnout_b   = (const float*)d_in[24];
    const float* head      = (const float*)d_in[25];

    float* out = (float*)d_out;
    float* logits = out;
    float* state_out;
    if (out_size >= NV + NL * 5 * D) {
        state_out = out + NV;
    } else {
        void* p = nullptr;
        cudaGetSymbolAddress(&p, g_state_scratch);
        state_out = (float*)p;
    }

    static bool attr_set = false;
    if (!attr_set) {
        cudaFuncSetAttribute(rwkv_fused, cudaFuncAttributeMaxDynamicSharedMemorySize,
                             SMEM_DYN);
        attr_set = true;
    }

    rwkv_fused<<<GRID, NTH, SMEM_DYN>>>(token, state, emb, ln0_w, ln0_b,
                                        ln1_w, ln1_b, ln2_w, ln2_b,
                                        att_key, att_value, att_recep, att_out,
                                        tm_k, tm_v, tm_r, t_first, t_decay,
                                        ffn_key, ffn_value, ffn_recep,
                                        ffn_tm_k, ffn_tm_r,
                                        lnout_w, lnout_b, head,
                                        logits, state_out);
}